// round 15
// baseline (speedup 1.0000x reference)
#include <cuda_runtime.h>

#define BB 4
#define NN 2000
#define GG 64
#define HH 512
#define WW 512
#define TT 200
#define PP 66
#define TPN 134          // T - P
#define MHH 28
#define MWW 28
#define EPSF 1e-8f

// XLA algebraic-simplifier style reciprocal constants (fp32, correctly rounded)
#define R_POS   (1.0f / 0.33f)
#define R_STD01 (1.0f / 0.1f)
#define R_STD02 (1.0f / 0.2f)
#define R_27    (1.0f / 27.0f)

// out layout (float32, concat of flattened outputs):
#define ROIS_OFF  0                   // B*T*4 = 3200
#define CLS_OFF   (BB*TT*4)           // 3200
#define DELTA_OFF (CLS_OFF + BB*TT)   // 4000
#define MASK_OFF  (DELTA_OFF + BB*TT*4) // 7200

// k_iou: 16 proposals per block (2 per warp), plus zero-fill blocks
#define IOU_BLKS  125
#define ZERO_BLKS 26
#define ZFILL_N4  (TPN*MHH*MWW/4)     // 26264 float4 per image

// k_masks sub-tiling: 4 sub-blocks per crop, 7 rows (196 px) each
#define MSUB      4
#define MROWS     (MHH/MSUB)          // 7
#define MPIX      (MROWS*MWW)         // 196

typedef unsigned long long ull;

// scratch (device globals; no allocations allowed)
__device__ float d_ioumax[BB*NN];
__device__ int   d_argmax[BB*NN];
__device__ float d_posbox[BB*PP*4];
__device__ int   d_posassign[BB*PP];
__device__ float d_posvalid[BB*PP];

__device__ __forceinline__ unsigned int ordf(float f) {
    unsigned int u = __float_as_uint(f);
    return (u & 0x80000000u) ? ~u : (u | 0x80000000u);
}
__device__ __forceinline__ float iordf(unsigned int u) {
    unsigned int r = (u & 0x80000000u) ? (u & 0x7FFFFFFFu) : ~u;
    return __uint_as_float(r);
}
#define ORDF_HALF 0xBF000000u   // ordf(0.5f)

// ---------------------------------------------------------------------------
// K1: 2 proposals per warp, IoU max + first-occurrence argmax; plus zero-fill
// of the always-zero mask rows t in [PP,TT) via 26 extra blocks per image.
// grid (IOU_BLKS + ZERO_BLKS, BB), 256 threads.
// ---------------------------------------------------------------------------
__global__ void __launch_bounds__(256) k_iou(const float* __restrict__ props,
                                             const int*   __restrict__ gids,
                                             const float* __restrict__ gboxes,
                                             float* __restrict__ out) {
    int b = blockIdx.y;
    int tid = threadIdx.x;

    if (blockIdx.x >= IOU_BLKS) {
        int zi = blockIdx.x - IOU_BLKS;
        float4* mz = (float4*)(out + MASK_OFF + (size_t)(b*TT + PP) * (MHH*MWW));
        float4 z = make_float4(0.f,0.f,0.f,0.f);
        for (int i = zi*256 + tid; i < ZFILL_N4; i += ZERO_BLKS*256) mz[i] = z;
        return;
    }

    int w = tid >> 5, lane = tid & 31;
    int pbase = blockIdx.x * 16 + 2*w;   // warp handles proposals pbase, pbase+1

    // lane-owned GT data, shared across both proposals
    int2 gid2 = ((const int2*)gids)[b*(GG/2) + lane];
    const float4* gb4 = (const float4*)gboxes + (size_t)b*GG + 2*lane;
    float4 gv[2];
    gv[0] = gb4[0];
    gv[1] = gb4[1];
    int gvalid[2] = { gid2.x > 0, gid2.y > 0 };
    float ga2[2];
    #pragma unroll
    for (int k = 0; k < 2; k++)
        ga2[k] = __fmul_rn(__fsub_rn(gv[k].z,gv[k].x), __fsub_rn(gv[k].w,gv[k].y));

    #pragma unroll
    for (int q = 0; q < 2; q++) {
        int p = pbase + q;
        float4 pv = ((const float4*)props)[(size_t)b*NN + p];
        float p0 = pv.x, p1 = pv.y, p2 = pv.z, p3 = pv.w;
        float ph = __fsub_rn(p2,p0), pw = __fsub_rn(p3,p1);

        float v[2];
        #pragma unroll
        for (int k = 0; k < 2; k++) {
            if (gvalid[k]) {
                float g0 = gv[k].x, g1 = gv[k].y, g2 = gv[k].z, g3 = gv[k].w;
                float yy1 = fmaxf(p0,g0), xx1 = fmaxf(p1,g1);
                float yy2 = fminf(p2,g2), xx2 = fminf(p3,g3);
                float ih = fmaxf(__fsub_rn(yy2,yy1), 0.0f);
                float iw = fmaxf(__fsub_rn(xx2,xx1), 0.0f);
                float inter = __fmul_rn(ih, iw);
                float s   = __fmaf_rn(ph, pw, ga2[k]);   // a1 + a2 (a1 fused)
                float uni = __fmaf_rn(-ih, iw, s);       // s - inter (fused)
                v[k] = __fdiv_rn(inter, fmaxf(uni, EPSF));
            } else {
                v[k] = -1.0f;
            }
        }
        float bv = v[0]; int bi = 2*lane;
        if (v[1] > bv) { bv = v[1]; bi = 2*lane + 1; }
        unsigned u = ordf(bv);
        unsigned m = __reduce_max_sync(0xFFFFFFFFu, u);
        unsigned bal = __ballot_sync(0xFFFFFFFFu, u == m);
        int src = __ffs(bal) - 1;
        int wi = __shfl_sync(0xFFFFFFFFu, bi, src);
        if (lane == 0) {
            d_ioumax[b*NN + p] = iordf(m);
            d_argmax[b*NN + p] = wi;
        }
    }
}

// ---------------------------------------------------------------------------
// Hybrid register/shfl/smem bitonic sort of 2048 keys, descending.
// ---------------------------------------------------------------------------
__device__ __forceinline__ void shflstep(ull &val, int j, bool desc, int lane) {
    ull o = __shfl_xor_sync(0xFFFFFFFFu, val, j);
    bool lower = (lane & j) == 0;
    bool keepmax = (lower == desc);
    bool takeo = keepmax ? (o > val) : (o < val);
    if (takeo) val = o;
}

__device__ void sort2048(ull r0, ull r1, ull* keys, int tid, int lane, int e0) {
    #pragma unroll
    for (int kk = 2; kk <= 32; kk <<= 1) {
        bool d0 = ((e0 & kk) == 0);
        bool d1 = (((e0 + 32) & kk) == 0);
        #pragma unroll
        for (int j = kk >> 1; j >= 1; j >>= 1) {
            shflstep(r0, j, d0, lane);
            shflstep(r1, j, d1, lane);
        }
    }
    {
        bool d = ((e0 & 64) == 0);
        ull hi = r0 > r1 ? r0 : r1, lo = r0 > r1 ? r1 : r0;
        if (d) { r0 = hi; r1 = lo; } else { r0 = lo; r1 = hi; }
        #pragma unroll
        for (int j = 16; j >= 1; j >>= 1) {
            shflstep(r0, j, d, lane);
            shflstep(r1, j, d, lane);
        }
    }
    for (int kk = 128; kk <= 2048; kk <<= 1) {
        keys[e0] = r0; keys[e0 + 32] = r1;
        __syncthreads();
        for (int j = kk >> 1; j >= 64; j >>= 1) {
            int e = (tid / j) * (2*j) + (tid % j);
            ull a = keys[e], c = keys[e + j];
            bool desc = ((e & kk) == 0);
            if ((a < c) == desc) { keys[e] = c; keys[e + j] = a; }
            __syncthreads();
        }
        r0 = keys[e0]; r1 = keys[e0 + 32];
        bool d = ((e0 & kk) == 0);
        ull hi = r0 > r1 ? r0 : r1, lo = r0 > r1 ? r1 : r0;
        if (d) { r0 = hi; r1 = lo; } else { r0 = lo; r1 = hi; }
        #pragma unroll
        for (int j = 16; j >= 1; j >>= 1) {
            shflstep(r0, j, d, lane);
            shflstep(r1, j, d, lane);
        }
    }
    keys[e0] = r0; keys[e0 + 32] = r1;
    __syncthreads();
}

// ---------------------------------------------------------------------------
// K2: sort + finish fused, grid (BB, 2): side 0 = positives, side 1 = negatives.
// ---------------------------------------------------------------------------
__global__ void __launch_bounds__(1024) k_sortfin(const float* __restrict__ props,
                                                  const int*   __restrict__ gids,
                                                  const float* __restrict__ gboxes,
                                                  float* __restrict__ out) {
    int b = blockIdx.x;
    int side = blockIdx.y;     // 0 = pos, 1 = neg
    int tid = threadIdx.x;
    int w = tid >> 5, lane = tid & 31;
    int e0 = w*64 + lane;      // e1 = e0 + 32
    __shared__ ull keys[2048];
    __shared__ int s_totpos;
    __shared__ int s_negn;

    if (tid == 0) s_totpos = 0;
    __syncthreads();

    const float* iom = d_ioumax + b*NN;
    bool in0 = (e0 < NN), in1 = (e0 + 32 < NN);
    float m0 = in0 ? iom[e0]      : 0.0f;
    float m1 = in1 ? iom[e0 + 32] : 0.0f;

    if (side == 0) {
        float v0 = (m0 >= 0.5f) ? m0 : -1.0f;
        float v1 = (m1 >= 0.5f) ? m1 : -1.0f;
        ull r0 = in0 ? (((ull)ordf(v0) << 32) | (unsigned)(2047 - e0))      : 0ull;
        ull r1 = in1 ? (((ull)ordf(v1) << 32) | (unsigned)(2047 - (e0+32))) : 0ull;
        sort2048(r0, r1, keys, tid, lane, e0);

        if (tid < PP) {
            ull k = keys[tid];
            int idx = 2047 - (int)(k & 0xFFFFFFFFull);
            float valid = ((unsigned)(k >> 32) >= ORDF_HALF) ? 1.0f : 0.0f;

            const float* pb = props + (size_t)(b*NN+idx)*4;
            float p0 = pb[0], p1 = pb[1], p2 = pb[2], p3 = pb[3];
            int as = d_argmax[b*NN + idx];
            float clsf = 0.0f;
            if (valid > 0.0f) clsf = (float)gids[b*GG + as];
            const float* gb = gboxes + (size_t)(b*GG+as)*4;
            float h  = fmaxf(__fsub_rn(p2,p0), EPSF);
            float w2 = fmaxf(__fsub_rn(p3,p1), EPSF);
            float cy = __fmaf_rn(0.5f, h,  p0);
            float cx = __fmaf_rn(0.5f, w2, p1);
            float gh = fmaxf(__fsub_rn(gb[2],gb[0]), EPSF);
            float gw = fmaxf(__fsub_rn(gb[3],gb[1]), EPSF);
            float gcy = __fmaf_rn(0.5f, gh, gb[0]);
            float gcx = __fmaf_rn(0.5f, gw, gb[1]);
            float d0 = __fdiv_rn(__fsub_rn(gcy,cy), h);
            float d1 = __fdiv_rn(__fsub_rn(gcx,cx), w2);
            float d2 = logf(__fdiv_rn(gh, h));
            float d3 = logf(__fdiv_rn(gw, w2));

            int row = b*TT + tid;
            out[ROIS_OFF + row*4 + 0] = __fmul_rn(p0, valid);
            out[ROIS_OFF + row*4 + 1] = __fmul_rn(p1, valid);
            out[ROIS_OFF + row*4 + 2] = __fmul_rn(p2, valid);
            out[ROIS_OFF + row*4 + 3] = __fmul_rn(p3, valid);
            out[CLS_OFF + row] = clsf;
            out[DELTA_OFF + row*4 + 0] = __fmul_rn(__fmul_rn(d0, R_STD01), valid);
            out[DELTA_OFF + row*4 + 1] = __fmul_rn(__fmul_rn(d1, R_STD01), valid);
            out[DELTA_OFF + row*4 + 2] = __fmul_rn(__fmul_rn(d2, R_STD02), valid);
            out[DELTA_OFF + row*4 + 3] = __fmul_rn(__fmul_rn(d3, R_STD02), valid);

            d_posbox[(b*PP+tid)*4+0] = p0;
            d_posbox[(b*PP+tid)*4+1] = p1;
            d_posbox[(b*PP+tid)*4+2] = p2;
            d_posbox[(b*PP+tid)*4+3] = p3;
            d_posassign[b*PP+tid] = as;
            d_posvalid[b*PP+tid]  = valid;
        }
    } else {
        {
            int c = (in0 && m0 >= 0.5f) + (in1 && m1 >= 0.5f);
            #pragma unroll
            for (int off = 16; off; off >>= 1) c += __shfl_xor_sync(0xFFFFFFFFu, c, off);
            if (lane == 0 && c) atomicAdd(&s_totpos, c);
        }
        float v0 = (m0 < 0.5f) ? (-m0) : -1000000000.0f;
        float v1 = (m1 < 0.5f) ? (-m1) : -1000000000.0f;
        ull r0 = in0 ? (((ull)ordf(v0) << 32) | (unsigned)(2047 - e0))      : 0ull;
        ull r1 = in1 ? (((ull)ordf(v1) << 32) | (unsigned)(2047 - (e0+32))) : 0ull;
        sort2048(r0, r1, keys, tid, lane, e0);   // ends with __syncthreads()

        if (tid == 0) {
            int pc = min(s_totpos, PP);                 // pos_count
            int negtotal = NN - s_totpos;               // count of m < 0.5
            int nt = (int)(__fmul_rn((float)pc, R_POS)) - pc;  // XLA: mul by 1/0.33
            nt = max(0, min(nt, TPN));
            s_negn = min(nt, negtotal);
        }
        __syncthreads();

        if (tid < TPN) {
            int idx = 2047 - (int)(keys[tid] & 0xFFFFFFFFull);
            float valid = (tid < s_negn) ? 1.0f : 0.0f;
            const float* pb = props + (size_t)(b*NN+idx)*4;
            int row = b*TT + PP + tid;
            out[ROIS_OFF + row*4 + 0] = __fmul_rn(pb[0], valid);
            out[ROIS_OFF + row*4 + 1] = __fmul_rn(pb[1], valid);
            out[ROIS_OFF + row*4 + 2] = __fmul_rn(pb[2], valid);
            out[ROIS_OFF + row*4 + 3] = __fmul_rn(pb[3], valid);
            out[CLS_OFF + row] = 0.0f;
            out[DELTA_OFF + row*4 + 0] = 0.0f;
            out[DELTA_OFF + row*4 + 1] = 0.0f;
            out[DELTA_OFF + row*4 + 2] = 0.0f;
            out[DELTA_OFF + row*4 + 3] = 0.0f;
        }
    }
}

// ---------------------------------------------------------------------------
// K3: mask crops, sub-tiled. grid (PP*MSUB, BB), 256 threads.
// Streaming loads (__ldcs): zero reuse, don't pollute caches.
// ---------------------------------------------------------------------------
__global__ void __launch_bounds__(256) k_masks(const float* __restrict__ gmasks,
                                               float* __restrict__ out) {
    int t = blockIdx.x / MSUB, sub = blockIdx.x % MSUB;
    int b = blockIdx.y;
    float* om = out + MASK_OFF + (size_t)(b*TT + t) * (MHH*MWW) + sub*MPIX;
    int tid = threadIdx.x;

    if (d_posvalid[b*PP + t] == 0.0f) {
        if (tid < MPIX/4) ((float4*)om)[tid] = make_float4(0.f,0.f,0.f,0.f);
        return;
    }
    int g = d_posassign[b*PP + t];

    __shared__ float wy[MROWS], wx[MWW];
    __shared__ int y0i[MROWS], y1i[MROWS], x0i[MWW], x1i[MWW];

    float by1 = d_posbox[(b*PP+t)*4+0];
    float bx1 = d_posbox[(b*PP+t)*4+1];
    float by2 = d_posbox[(b*PP+t)*4+2];
    float bx2 = d_posbox[(b*PP+t)*4+3];

    if (tid < MROWS) {
        int i = sub*MROWS + tid;            // global row index
        float s  = __fmul_rn(__fmul_rn(__fsub_rn(by2,by1), (float)i), R_27);
        float yv = __fmul_rn(__fadd_rn(by1, s), 511.0f);
        float y0 = floorf(yv);
        wy[tid] = __fsub_rn(yv, y0);
        float c0 = fminf(fmaxf(y0, 0.0f), 511.0f);
        float c1 = fminf(fmaxf(__fadd_rn(y0, 1.0f), 0.0f), 511.0f);
        y0i[tid] = (int)c0; y1i[tid] = (int)c1;
    } else if (tid < MROWS + MWW) {
        int j = tid - MROWS;
        float s  = __fmul_rn(__fmul_rn(__fsub_rn(bx2,bx1), (float)j), R_27);
        float xv = __fmul_rn(__fadd_rn(bx1, s), 511.0f);
        float x0 = floorf(xv);
        wx[j] = __fsub_rn(xv, x0);
        float c0 = fminf(fmaxf(x0, 0.0f), 511.0f);
        float c1 = fminf(fmaxf(__fadd_rn(x0, 1.0f), 0.0f), 511.0f);
        x0i[j] = (int)c0; x1i[j] = (int)c1;
    }
    __syncthreads();

    if (tid < MPIX) {
        int ly = tid / MWW, xx = tid % MWW;   // local row, column
        const float* base = gmasks + (size_t)b*HH*WW*GG + g;
        int ya = y0i[ly], yb = y1i[ly], xa = x0i[xx], xb = x1i[xx];
        float v00 = __ldcs(&base[((size_t)ya*WW + xa)*GG]);
        float v01 = __ldcs(&base[((size_t)ya*WW + xb)*GG]);
        float v10 = __ldcs(&base[((size_t)yb*WW + xa)*GG]);
        float v11 = __ldcs(&base[((size_t)yb*WW + xb)*GG]);
        float fwx = wx[xx], fwy = wy[ly];
        float owx = __fsub_rn(1.0f, fwx);
        float owy = __fsub_rn(1.0f, fwy);
        float top = __fmaf_rn(v00, owx, __fmul_rn(v01, fwx));
        float bot = __fmaf_rn(v10, owx, __fmul_rn(v11, fwx));
        float r   = __fmaf_rn(top, owy, __fmul_rn(bot, fwy));
        om[tid] = rintf(r);
    }
}

// ---------------------------------------------------------------------------
extern "C" void kernel_launch(void* const* d_in, const int* in_sizes, int n_in,
                              void* d_out, int out_size) {
    const float* props  = (const float*)d_in[0];  // (B, N, 4)
    const int*   gids   = (const int*)  d_in[1];  // (B, G)
    const float* gboxes = (const float*)d_in[2];  // (B, G, 4)
    const float* gmasks = (const float*)d_in[3];  // (B, H, W, G)
    float* out = (float*)d_out;

    dim3 g1(IOU_BLKS + ZERO_BLKS, BB);
    k_iou<<<g1, 256>>>(props, gids, gboxes, out);
    dim3 g2(BB, 2);
    k_sortfin<<<g2, 1024>>>(props, gids, gboxes, out);
    dim3 g3(PP*MSUB, BB);
    k_masks<<<g3, 256>>>(gmasks, out);
}

// round 16
// speedup vs baseline: 1.0056x; 1.0056x over previous
#include <cuda_runtime.h>

#define BB 4
#define NN 2000
#define GG 64
#define HH 512
#define WW 512
#define TT 200
#define PP 66
#define TPN 134          // T - P
#define MHH 28
#define MWW 28
#define EPSF 1e-8f

// XLA algebraic-simplifier style reciprocal constants (fp32, correctly rounded)
#define R_POS   (1.0f / 0.33f)
#define R_STD01 (1.0f / 0.1f)
#define R_STD02 (1.0f / 0.2f)
#define R_27    (1.0f / 27.0f)

// out layout (float32, concat of flattened outputs):
#define ROIS_OFF  0                   // B*T*4 = 3200
#define CLS_OFF   (BB*TT*4)           // 3200
#define DELTA_OFF (CLS_OFF + BB*TT)   // 4000
#define MASK_OFF  (DELTA_OFF + BB*TT*4) // 7200

// k_iou grid extension for dead-mask zero-fill (R14 config: 1 proposal/warp)
#define IOU_BLKS  250
#define ZERO_BLKS 26
#define ZFILL_N4  (TPN*MHH*MWW/4)     // 26264 float4 per image

// k_masks sub-tiling: 4 sub-blocks per crop, 7 rows (196 px) each
#define MSUB      4
#define MROWS     (MHH/MSUB)          // 7
#define MPIX      (MROWS*MWW)         // 196

typedef unsigned long long ull;

// scratch (device globals; no allocations allowed)
__device__ float d_ioumax[BB*NN];
__device__ int   d_argmax[BB*NN];
__device__ float d_posbox[BB*PP*4];
__device__ int   d_posassign[BB*PP];
__device__ float d_posvalid[BB*PP];

__device__ __forceinline__ unsigned int ordf(float f) {
    unsigned int u = __float_as_uint(f);
    return (u & 0x80000000u) ? ~u : (u | 0x80000000u);
}
__device__ __forceinline__ float iordf(unsigned int u) {
    unsigned int r = (u & 0x80000000u) ? (u & 0x7FFFFFFFu) : ~u;
    return __uint_as_float(r);
}
#define ORDF_HALF 0xBF000000u   // ordf(0.5f)

// ---------------------------------------------------------------------------
// K1: warp-per-proposal IoU max + first-occurrence argmax (R14 best config),
// plus zero-fill of always-zero mask rows t in [PP,TT) via 26 extra blocks.
// grid (IOU_BLKS + ZERO_BLKS, BB), 256 threads. Vectorized loads.
// ---------------------------------------------------------------------------
__global__ void __launch_bounds__(256) k_iou(const float* __restrict__ props,
                                             const int*   __restrict__ gids,
                                             const float* __restrict__ gboxes,
                                             float* __restrict__ out) {
    int b = blockIdx.y;
    int tid = threadIdx.x;

    if (blockIdx.x >= IOU_BLKS) {
        int zi = blockIdx.x - IOU_BLKS;
        float4* mz = (float4*)(out + MASK_OFF + (size_t)(b*TT + PP) * (MHH*MWW));
        float4 z = make_float4(0.f,0.f,0.f,0.f);
        for (int i = zi*256 + tid; i < ZFILL_N4; i += ZERO_BLKS*256)
            __stcs(&mz[i], z);
        return;
    }

    int w = tid >> 5, lane = tid & 31;
    int p = blockIdx.x * 8 + w;          // 250*8 = 2000 proposals

    // vectorized loads: 1x float4 (proposal), 1x int2 (ids), 2x float4 (GT boxes)
    float4 pv = ((const float4*)props)[(size_t)b*NN + p];
    float p0 = pv.x, p1 = pv.y, p2 = pv.z, p3 = pv.w;
    float ph = __fsub_rn(p2,p0), pw = __fsub_rn(p3,p1);

    int2 gid2 = ((const int2*)gids)[b*(GG/2) + lane];
    const float4* gb4 = (const float4*)gboxes + (size_t)b*GG + 2*lane;
    float4 gv[2];
    gv[0] = gb4[0];
    gv[1] = gb4[1];
    int gvalid[2] = { gid2.x > 0, gid2.y > 0 };

    float v[2];
    #pragma unroll
    for (int k = 0; k < 2; k++) {
        if (gvalid[k]) {
            float g0 = gv[k].x, g1 = gv[k].y, g2 = gv[k].z, g3 = gv[k].w;
            float a2 = __fmul_rn(__fsub_rn(g2,g0), __fsub_rn(g3,g1));
            float yy1 = fmaxf(p0,g0), xx1 = fmaxf(p1,g1);
            float yy2 = fminf(p2,g2), xx2 = fminf(p3,g3);
            float ih = fmaxf(__fsub_rn(yy2,yy1), 0.0f);
            float iw = fmaxf(__fsub_rn(xx2,xx1), 0.0f);
            float inter = __fmul_rn(ih, iw);
            float s   = __fmaf_rn(ph, pw, a2);       // a1 + a2 (a1 fused)
            float uni = __fmaf_rn(-ih, iw, s);       // s - inter (fused)
            v[k] = __fdiv_rn(inter, fmaxf(uni, EPSF));
        } else {
            v[k] = -1.0f;
        }
    }
    float bv = v[0]; int bi = 2*lane;
    if (v[1] > bv) { bv = v[1]; bi = 2*lane + 1; }
    unsigned u = ordf(bv);
    unsigned m = __reduce_max_sync(0xFFFFFFFFu, u);
    unsigned bal = __ballot_sync(0xFFFFFFFFu, u == m);
    int src = __ffs(bal) - 1;
    int wi = __shfl_sync(0xFFFFFFFFu, bi, src);
    if (lane == 0) {
        d_ioumax[b*NN + p] = iordf(m);
        d_argmax[b*NN + p] = wi;
    }
}

// ---------------------------------------------------------------------------
// Hybrid register/shfl/smem bitonic sort of 2048 keys, descending.
// ---------------------------------------------------------------------------
__device__ __forceinline__ void shflstep(ull &val, int j, bool desc, int lane) {
    ull o = __shfl_xor_sync(0xFFFFFFFFu, val, j);
    bool lower = (lane & j) == 0;
    bool keepmax = (lower == desc);
    bool takeo = keepmax ? (o > val) : (o < val);
    if (takeo) val = o;
}

__device__ void sort2048(ull r0, ull r1, ull* keys, int tid, int lane, int e0) {
    #pragma unroll
    for (int kk = 2; kk <= 32; kk <<= 1) {
        bool d0 = ((e0 & kk) == 0);
        bool d1 = (((e0 + 32) & kk) == 0);
        #pragma unroll
        for (int j = kk >> 1; j >= 1; j >>= 1) {
            shflstep(r0, j, d0, lane);
            shflstep(r1, j, d1, lane);
        }
    }
    {
        bool d = ((e0 & 64) == 0);
        ull hi = r0 > r1 ? r0 : r1, lo = r0 > r1 ? r1 : r0;
        if (d) { r0 = hi; r1 = lo; } else { r0 = lo; r1 = hi; }
        #pragma unroll
        for (int j = 16; j >= 1; j >>= 1) {
            shflstep(r0, j, d, lane);
            shflstep(r1, j, d, lane);
        }
    }
    for (int kk = 128; kk <= 2048; kk <<= 1) {
        keys[e0] = r0; keys[e0 + 32] = r1;
        __syncthreads();
        for (int j = kk >> 1; j >= 64; j >>= 1) {
            int e = (tid / j) * (2*j) + (tid % j);
            ull a = keys[e], c = keys[e + j];
            bool desc = ((e & kk) == 0);
            if ((a < c) == desc) { keys[e] = c; keys[e + j] = a; }
            __syncthreads();
        }
        r0 = keys[e0]; r1 = keys[e0 + 32];
        bool d = ((e0 & kk) == 0);
        ull hi = r0 > r1 ? r0 : r1, lo = r0 > r1 ? r1 : r0;
        if (d) { r0 = hi; r1 = lo; } else { r0 = lo; r1 = hi; }
        #pragma unroll
        for (int j = 16; j >= 1; j >>= 1) {
            shflstep(r0, j, d, lane);
            shflstep(r1, j, d, lane);
        }
    }
    keys[e0] = r0; keys[e0 + 32] = r1;
    __syncthreads();
}

// ---------------------------------------------------------------------------
// K2: sort + finish fused, grid (BB, 2): side 0 = positives, side 1 = negatives.
// ---------------------------------------------------------------------------
__global__ void __launch_bounds__(1024) k_sortfin(const float* __restrict__ props,
                                                  const int*   __restrict__ gids,
                                                  const float* __restrict__ gboxes,
                                                  float* __restrict__ out) {
    int b = blockIdx.x;
    int side = blockIdx.y;     // 0 = pos, 1 = neg
    int tid = threadIdx.x;
    int w = tid >> 5, lane = tid & 31;
    int e0 = w*64 + lane;      // e1 = e0 + 32
    __shared__ ull keys[2048];
    __shared__ int s_totpos;
    __shared__ int s_negn;

    if (tid == 0) s_totpos = 0;
    __syncthreads();

    const float* iom = d_ioumax + b*NN;
    bool in0 = (e0 < NN), in1 = (e0 + 32 < NN);
    float m0 = in0 ? iom[e0]      : 0.0f;
    float m1 = in1 ? iom[e0 + 32] : 0.0f;

    if (side == 0) {
        float v0 = (m0 >= 0.5f) ? m0 : -1.0f;
        float v1 = (m1 >= 0.5f) ? m1 : -1.0f;
        ull r0 = in0 ? (((ull)ordf(v0) << 32) | (unsigned)(2047 - e0))      : 0ull;
        ull r1 = in1 ? (((ull)ordf(v1) << 32) | (unsigned)(2047 - (e0+32))) : 0ull;
        sort2048(r0, r1, keys, tid, lane, e0);

        if (tid < PP) {
            ull k = keys[tid];
            int idx = 2047 - (int)(k & 0xFFFFFFFFull);
            float valid = ((unsigned)(k >> 32) >= ORDF_HALF) ? 1.0f : 0.0f;

            const float* pb = props + (size_t)(b*NN+idx)*4;
            float p0 = pb[0], p1 = pb[1], p2 = pb[2], p3 = pb[3];
            int as = d_argmax[b*NN + idx];
            float clsf = 0.0f;
            if (valid > 0.0f) clsf = (float)gids[b*GG + as];
            const float* gb = gboxes + (size_t)(b*GG+as)*4;
            float h  = fmaxf(__fsub_rn(p2,p0), EPSF);
            float w2 = fmaxf(__fsub_rn(p3,p1), EPSF);
            float cy = __fmaf_rn(0.5f, h,  p0);
            float cx = __fmaf_rn(0.5f, w2, p1);
            float gh = fmaxf(__fsub_rn(gb[2],gb[0]), EPSF);
            float gw = fmaxf(__fsub_rn(gb[3],gb[1]), EPSF);
            float gcy = __fmaf_rn(0.5f, gh, gb[0]);
            float gcx = __fmaf_rn(0.5f, gw, gb[1]);
            float d0 = __fdiv_rn(__fsub_rn(gcy,cy), h);
            float d1 = __fdiv_rn(__fsub_rn(gcx,cx), w2);
            float d2 = logf(__fdiv_rn(gh, h));
            float d3 = logf(__fdiv_rn(gw, w2));

            int row = b*TT + tid;
            out[ROIS_OFF + row*4 + 0] = __fmul_rn(p0, valid);
            out[ROIS_OFF + row*4 + 1] = __fmul_rn(p1, valid);
            out[ROIS_OFF + row*4 + 2] = __fmul_rn(p2, valid);
            out[ROIS_OFF + row*4 + 3] = __fmul_rn(p3, valid);
            out[CLS_OFF + row] = clsf;
            out[DELTA_OFF + row*4 + 0] = __fmul_rn(__fmul_rn(d0, R_STD01), valid);
            out[DELTA_OFF + row*4 + 1] = __fmul_rn(__fmul_rn(d1, R_STD01), valid);
            out[DELTA_OFF + row*4 + 2] = __fmul_rn(__fmul_rn(d2, R_STD02), valid);
            out[DELTA_OFF + row*4 + 3] = __fmul_rn(__fmul_rn(d3, R_STD02), valid);

            d_posbox[(b*PP+tid)*4+0] = p0;
            d_posbox[(b*PP+tid)*4+1] = p1;
            d_posbox[(b*PP+tid)*4+2] = p2;
            d_posbox[(b*PP+tid)*4+3] = p3;
            d_posassign[b*PP+tid] = as;
            d_posvalid[b*PP+tid]  = valid;
        }
    } else {
        {
            int c = (in0 && m0 >= 0.5f) + (in1 && m1 >= 0.5f);
            #pragma unroll
            for (int off = 16; off; off >>= 1) c += __shfl_xor_sync(0xFFFFFFFFu, c, off);
            if (lane == 0 && c) atomicAdd(&s_totpos, c);
        }
        float v0 = (m0 < 0.5f) ? (-m0) : -1000000000.0f;
        float v1 = (m1 < 0.5f) ? (-m1) : -1000000000.0f;
        ull r0 = in0 ? (((ull)ordf(v0) << 32) | (unsigned)(2047 - e0))      : 0ull;
        ull r1 = in1 ? (((ull)ordf(v1) << 32) | (unsigned)(2047 - (e0+32))) : 0ull;
        sort2048(r0, r1, keys, tid, lane, e0);   // ends with __syncthreads()

        if (tid == 0) {
            int pc = min(s_totpos, PP);                 // pos_count
            int negtotal = NN - s_totpos;               // count of m < 0.5
            int nt = (int)(__fmul_rn((float)pc, R_POS)) - pc;  // XLA: mul by 1/0.33
            nt = max(0, min(nt, TPN));
            s_negn = min(nt, negtotal);
        }
        __syncthreads();

        if (tid < TPN) {
            int idx = 2047 - (int)(keys[tid] & 0xFFFFFFFFull);
            float valid = (tid < s_negn) ? 1.0f : 0.0f;
            const float* pb = props + (size_t)(b*NN+idx)*4;
            int row = b*TT + PP + tid;
            out[ROIS_OFF + row*4 + 0] = __fmul_rn(pb[0], valid);
            out[ROIS_OFF + row*4 + 1] = __fmul_rn(pb[1], valid);
            out[ROIS_OFF + row*4 + 2] = __fmul_rn(pb[2], valid);
            out[ROIS_OFF + row*4 + 3] = __fmul_rn(pb[3], valid);
            out[CLS_OFF + row] = 0.0f;
            out[DELTA_OFF + row*4 + 0] = 0.0f;
            out[DELTA_OFF + row*4 + 1] = 0.0f;
            out[DELTA_OFF + row*4 + 2] = 0.0f;
            out[DELTA_OFF + row*4 + 3] = 0.0f;
        }
    }
}

// ---------------------------------------------------------------------------
// K3: mask crops, sub-tiled. grid (PP*MSUB, BB), 256 threads.
// Streaming loads + streaming stores: zero reuse either way.
// ---------------------------------------------------------------------------
__global__ void __launch_bounds__(256) k_masks(const float* __restrict__ gmasks,
                                               float* __restrict__ out) {
    int t = blockIdx.x / MSUB, sub = blockIdx.x % MSUB;
    int b = blockIdx.y;
    float* om = out + MASK_OFF + (size_t)(b*TT + t) * (MHH*MWW) + sub*MPIX;
    int tid = threadIdx.x;

    if (d_posvalid[b*PP + t] == 0.0f) {
        if (tid < MPIX/4) __stcs(&((float4*)om)[tid], make_float4(0.f,0.f,0.f,0.f));
        return;
    }
    int g = d_posassign[b*PP + t];

    __shared__ float wy[MROWS], wx[MWW];
    __shared__ int y0i[MROWS], y1i[MROWS], x0i[MWW], x1i[MWW];

    float by1 = d_posbox[(b*PP+t)*4+0];
    float bx1 = d_posbox[(b*PP+t)*4+1];
    float by2 = d_posbox[(b*PP+t)*4+2];
    float bx2 = d_posbox[(b*PP+t)*4+3];

    if (tid < MROWS) {
        int i = sub*MROWS + tid;            // global row index
        float s  = __fmul_rn(__fmul_rn(__fsub_rn(by2,by1), (float)i), R_27);
        float yv = __fmul_rn(__fadd_rn(by1, s), 511.0f);
        float y0 = floorf(yv);
        wy[tid] = __fsub_rn(yv, y0);
        float c0 = fminf(fmaxf(y0, 0.0f), 511.0f);
        float c1 = fminf(fmaxf(__fadd_rn(y0, 1.0f), 0.0f), 511.0f);
        y0i[tid] = (int)c0; y1i[tid] = (int)c1;
    } else if (tid < MROWS + MWW) {
        int j = tid - MROWS;
        float s  = __fmul_rn(__fmul_rn(__fsub_rn(bx2,bx1), (float)j), R_27);
        float xv = __fmul_rn(__fadd_rn(bx1, s), 511.0f);
        float x0 = floorf(xv);
        wx[j] = __fsub_rn(xv, x0);
        float c0 = fminf(fmaxf(x0, 0.0f), 511.0f);
        float c1 = fminf(fmaxf(__fadd_rn(x0, 1.0f), 0.0f), 511.0f);
        x0i[j] = (int)c0; x1i[j] = (int)c1;
    }
    __syncthreads();

    if (tid < MPIX) {
        int ly = tid / MWW, xx = tid % MWW;   // local row, column
        const float* base = gmasks + (size_t)b*HH*WW*GG + g;
        int ya = y0i[ly], yb = y1i[ly], xa = x0i[xx], xb = x1i[xx];
        float v00 = __ldcs(&base[((size_t)ya*WW + xa)*GG]);
        float v01 = __ldcs(&base[((size_t)ya*WW + xb)*GG]);
        float v10 = __ldcs(&base[((size_t)yb*WW + xa)*GG]);
        float v11 = __ldcs(&base[((size_t)yb*WW + xb)*GG]);
        float fwx = wx[xx], fwy = wy[ly];
        float owx = __fsub_rn(1.0f, fwx);
        float owy = __fsub_rn(1.0f, fwy);
        float top = __fmaf_rn(v00, owx, __fmul_rn(v01, fwx));
        float bot = __fmaf_rn(v10, owx, __fmul_rn(v11, fwx));
        float r   = __fmaf_rn(top, owy, __fmul_rn(bot, fwy));
        __stcs(&om[tid], rintf(r));
    }
}

// ---------------------------------------------------------------------------
extern "C" void kernel_launch(void* const* d_in, const int* in_sizes, int n_in,
                              void* d_out, int out_size) {
    const float* props  = (const float*)d_in[0];  // (B, N, 4)
    const int*   gids   = (const int*)  d_in[1];  // (B, G)
    const float* gboxes = (const float*)d_in[2];  // (B, G, 4)
    const float* gmasks = (const float*)d_in[3];  // (B, H, W, G)
    float* out = (float*)d_out;

    dim3 g1(IOU_BLKS + ZERO_BLKS, BB);
    k_iou<<<g1, 256>>>(props, gids, gboxes, out);
    dim3 g2(BB, 2);
    k_sortfin<<<g2, 1024>>>(props, gids, gboxes, out);
    dim3 g3(PP*MSUB, BB);
    k_masks<<<g3, 256>>>(gmasks, out);
}

// round 17
// speedup vs baseline: 1.0465x; 1.0407x over previous
#include <cuda_runtime.h>

#define BB 4
#define NN 2000
#define GG 64
#define HH 512
#define WW 512
#define TT 200
#define PP 66
#define TPN 134          // T - P
#define MHH 28
#define MWW 28
#define EPSF 1e-8f

// XLA algebraic-simplifier style reciprocal constants (fp32, correctly rounded)
#define R_POS   (1.0f / 0.33f)
#define R_STD01 (1.0f / 0.1f)
#define R_STD02 (1.0f / 0.2f)
#define R_27    (1.0f / 27.0f)

// out layout (float32, concat of flattened outputs):
#define ROIS_OFF  0                   // B*T*4 = 3200
#define CLS_OFF   (BB*TT*4)           // 3200
#define DELTA_OFF (CLS_OFF + BB*TT)   // 4000
#define MASK_OFF  (DELTA_OFF + BB*TT*4) // 7200

// k_iou grid extension for dead-mask zero-fill
#define IOU_BLKS  250
#define ZERO_BLKS 26
#define ZFILL_N4  (TPN*MHH*MWW/4)     // 26264 float4 per image

// k_masks sub-tiling: 4 sub-blocks per crop, 7 rows (196 px) each
#define MSUB      4
#define MROWS     (MHH/MSUB)          // 7
#define MPIX      (MROWS*MWW)         // 196

typedef unsigned long long ull;

// scratch (device globals; no allocations allowed)
__device__ float d_ioumax[BB*NN];
__device__ int   d_argmax[BB*NN];
__device__ float d_posbox[BB*PP*4];
__device__ int   d_posassign[BB*PP];
__device__ float d_posvalid[BB*PP];

__device__ __forceinline__ unsigned int ordf(float f) {
    unsigned int u = __float_as_uint(f);
    return (u & 0x80000000u) ? ~u : (u | 0x80000000u);
}
__device__ __forceinline__ float iordf(unsigned int u) {
    unsigned int r = (u & 0x80000000u) ? (u & 0x7FFFFFFFu) : ~u;
    return __uint_as_float(r);
}
#define ORDF_HALF 0xBF000000u   // ordf(0.5f)

// ---------------------------------------------------------------------------
// K1: warp-per-proposal IoU max + first-occurrence argmax, plus zero-fill of
// the always-zero mask rows t in [PP,TT) using 26 extra blocks per image.
// grid (IOU_BLKS + ZERO_BLKS, BB), 256 threads. Vectorized loads.
// ---------------------------------------------------------------------------
__global__ void __launch_bounds__(256) k_iou(const float* __restrict__ props,
                                             const int*   __restrict__ gids,
                                             const float* __restrict__ gboxes,
                                             float* __restrict__ out) {
    int b = blockIdx.y;
    int tid = threadIdx.x;

    if (blockIdx.x >= IOU_BLKS) {
        int zi = blockIdx.x - IOU_BLKS;
        float4* mz = (float4*)(out + MASK_OFF + (size_t)(b*TT + PP) * (MHH*MWW));
        float4 z = make_float4(0.f,0.f,0.f,0.f);
        for (int i = zi*256 + tid; i < ZFILL_N4; i += ZERO_BLKS*256) mz[i] = z;
        return;
    }

    int w = tid >> 5, lane = tid & 31;
    int p = blockIdx.x * 8 + w;          // 250*8 = 2000 proposals

    // vectorized loads: 1x float4 (proposal), 1x int2 (ids), 2x float4 (GT boxes)
    float4 pv = ((const float4*)props)[(size_t)b*NN + p];
    float p0 = pv.x, p1 = pv.y, p2 = pv.z, p3 = pv.w;
    float ph = __fsub_rn(p2,p0), pw = __fsub_rn(p3,p1);

    int2 gid2 = ((const int2*)gids)[b*(GG/2) + lane];
    const float4* gb4 = (const float4*)gboxes + (size_t)b*GG + 2*lane;
    float4 gv[2];
    gv[0] = gb4[0];
    gv[1] = gb4[1];
    int gvalid[2] = { gid2.x > 0, gid2.y > 0 };

    float v[2];
    #pragma unroll
    for (int k = 0; k < 2; k++) {
        if (gvalid[k]) {
            float g0 = gv[k].x, g1 = gv[k].y, g2 = gv[k].z, g3 = gv[k].w;
            float a2 = __fmul_rn(__fsub_rn(g2,g0), __fsub_rn(g3,g1));
            float yy1 = fmaxf(p0,g0), xx1 = fmaxf(p1,g1);
            float yy2 = fminf(p2,g2), xx2 = fminf(p3,g3);
            float ih = fmaxf(__fsub_rn(yy2,yy1), 0.0f);
            float iw = fmaxf(__fsub_rn(xx2,xx1), 0.0f);
            float inter = __fmul_rn(ih, iw);
            float s   = __fmaf_rn(ph, pw, a2);       // a1 + a2 (a1 fused)
            float uni = __fmaf_rn(-ih, iw, s);       // s - inter (fused)
            v[k] = __fdiv_rn(inter, fmaxf(uni, EPSF));
        } else {
            v[k] = -1.0f;
        }
    }
    float bv = v[0]; int bi = 2*lane;
    if (v[1] > bv) { bv = v[1]; bi = 2*lane + 1; }
    unsigned u = ordf(bv);
    unsigned m = __reduce_max_sync(0xFFFFFFFFu, u);
    unsigned bal = __ballot_sync(0xFFFFFFFFu, u == m);
    int src = __ffs(bal) - 1;
    int wi = __shfl_sync(0xFFFFFFFFu, bi, src);
    if (lane == 0) {
        d_ioumax[b*NN + p] = iordf(m);
        d_argmax[b*NN + p] = wi;
    }
}

// ---------------------------------------------------------------------------
// Hybrid register/shfl/smem bitonic sort of 2048 keys, descending.
// ---------------------------------------------------------------------------
__device__ __forceinline__ void shflstep(ull &val, int j, bool desc, int lane) {
    ull o = __shfl_xor_sync(0xFFFFFFFFu, val, j);
    bool lower = (lane & j) == 0;
    bool keepmax = (lower == desc);
    bool takeo = keepmax ? (o > val) : (o < val);
    if (takeo) val = o;
}

__device__ void sort2048(ull r0, ull r1, ull* keys, int tid, int lane, int e0) {
    #pragma unroll
    for (int kk = 2; kk <= 32; kk <<= 1) {
        bool d0 = ((e0 & kk) == 0);
        bool d1 = (((e0 + 32) & kk) == 0);
        #pragma unroll
        for (int j = kk >> 1; j >= 1; j >>= 1) {
            shflstep(r0, j, d0, lane);
            shflstep(r1, j, d1, lane);
        }
    }
    {
        bool d = ((e0 & 64) == 0);
        ull hi = r0 > r1 ? r0 : r1, lo = r0 > r1 ? r1 : r0;
        if (d) { r0 = hi; r1 = lo; } else { r0 = lo; r1 = hi; }
        #pragma unroll
        for (int j = 16; j >= 1; j >>= 1) {
            shflstep(r0, j, d, lane);
            shflstep(r1, j, d, lane);
        }
    }
    for (int kk = 128; kk <= 2048; kk <<= 1) {
        keys[e0] = r0; keys[e0 + 32] = r1;
        __syncthreads();
        for (int j = kk >> 1; j >= 64; j >>= 1) {
            int e = (tid / j) * (2*j) + (tid % j);
            ull a = keys[e], c = keys[e + j];
            bool desc = ((e & kk) == 0);
            if ((a < c) == desc) { keys[e] = c; keys[e + j] = a; }
            __syncthreads();
        }
        r0 = keys[e0]; r1 = keys[e0 + 32];
        bool d = ((e0 & kk) == 0);
        ull hi = r0 > r1 ? r0 : r1, lo = r0 > r1 ? r1 : r0;
        if (d) { r0 = hi; r1 = lo; } else { r0 = lo; r1 = hi; }
        #pragma unroll
        for (int j = 16; j >= 1; j >>= 1) {
            shflstep(r0, j, d, lane);
            shflstep(r1, j, d, lane);
        }
    }
    keys[e0] = r0; keys[e0 + 32] = r1;
    __syncthreads();
}

// ---------------------------------------------------------------------------
// K2: sort + finish fused, grid (BB, 2): side 0 = positives, side 1 = negatives.
// ---------------------------------------------------------------------------
__global__ void __launch_bounds__(1024) k_sortfin(const float* __restrict__ props,
                                                  const int*   __restrict__ gids,
                                                  const float* __restrict__ gboxes,
                                                  float* __restrict__ out) {
    int b = blockIdx.x;
    int side = blockIdx.y;     // 0 = pos, 1 = neg
    int tid = threadIdx.x;
    int w = tid >> 5, lane = tid & 31;
    int e0 = w*64 + lane;      // e1 = e0 + 32
    __shared__ ull keys[2048];
    __shared__ int s_totpos;
    __shared__ int s_negn;

    if (tid == 0) s_totpos = 0;
    __syncthreads();

    const float* iom = d_ioumax + b*NN;
    bool in0 = (e0 < NN), in1 = (e0 + 32 < NN);
    float m0 = in0 ? iom[e0]      : 0.0f;
    float m1 = in1 ? iom[e0 + 32] : 0.0f;

    if (side == 0) {
        float v0 = (m0 >= 0.5f) ? m0 : -1.0f;
        float v1 = (m1 >= 0.5f) ? m1 : -1.0f;
        ull r0 = in0 ? (((ull)ordf(v0) << 32) | (unsigned)(2047 - e0))      : 0ull;
        ull r1 = in1 ? (((ull)ordf(v1) << 32) | (unsigned)(2047 - (e0+32))) : 0ull;
        sort2048(r0, r1, keys, tid, lane, e0);

        if (tid < PP) {
            ull k = keys[tid];
            int idx = 2047 - (int)(k & 0xFFFFFFFFull);
            float valid = ((unsigned)(k >> 32) >= ORDF_HALF) ? 1.0f : 0.0f;

            const float* pb = props + (size_t)(b*NN+idx)*4;
            float p0 = pb[0], p1 = pb[1], p2 = pb[2], p3 = pb[3];
            int as = d_argmax[b*NN + idx];
            float clsf = 0.0f;
            if (valid > 0.0f) clsf = (float)gids[b*GG + as];
            const float* gb = gboxes + (size_t)(b*GG+as)*4;
            float h  = fmaxf(__fsub_rn(p2,p0), EPSF);
            float w2 = fmaxf(__fsub_rn(p3,p1), EPSF);
            float cy = __fmaf_rn(0.5f, h,  p0);
            float cx = __fmaf_rn(0.5f, w2, p1);
            float gh = fmaxf(__fsub_rn(gb[2],gb[0]), EPSF);
            float gw = fmaxf(__fsub_rn(gb[3],gb[1]), EPSF);
            float gcy = __fmaf_rn(0.5f, gh, gb[0]);
            float gcx = __fmaf_rn(0.5f, gw, gb[1]);
            float d0 = __fdiv_rn(__fsub_rn(gcy,cy), h);
            float d1 = __fdiv_rn(__fsub_rn(gcx,cx), w2);
            float d2 = logf(__fdiv_rn(gh, h));
            float d3 = logf(__fdiv_rn(gw, w2));

            int row = b*TT + tid;
            out[ROIS_OFF + row*4 + 0] = __fmul_rn(p0, valid);
            out[ROIS_OFF + row*4 + 1] = __fmul_rn(p1, valid);
            out[ROIS_OFF + row*4 + 2] = __fmul_rn(p2, valid);
            out[ROIS_OFF + row*4 + 3] = __fmul_rn(p3, valid);
            out[CLS_OFF + row] = clsf;
            out[DELTA_OFF + row*4 + 0] = __fmul_rn(__fmul_rn(d0, R_STD01), valid);
            out[DELTA_OFF + row*4 + 1] = __fmul_rn(__fmul_rn(d1, R_STD01), valid);
            out[DELTA_OFF + row*4 + 2] = __fmul_rn(__fmul_rn(d2, R_STD02), valid);
            out[DELTA_OFF + row*4 + 3] = __fmul_rn(__fmul_rn(d3, R_STD02), valid);

            d_posbox[(b*PP+tid)*4+0] = p0;
            d_posbox[(b*PP+tid)*4+1] = p1;
            d_posbox[(b*PP+tid)*4+2] = p2;
            d_posbox[(b*PP+tid)*4+3] = p3;
            d_posassign[b*PP+tid] = as;
            d_posvalid[b*PP+tid]  = valid;
        }
    } else {
        {
            int c = (in0 && m0 >= 0.5f) + (in1 && m1 >= 0.5f);
            #pragma unroll
            for (int off = 16; off; off >>= 1) c += __shfl_xor_sync(0xFFFFFFFFu, c, off);
            if (lane == 0 && c) atomicAdd(&s_totpos, c);
        }
        float v0 = (m0 < 0.5f) ? (-m0) : -1000000000.0f;
        float v1 = (m1 < 0.5f) ? (-m1) : -1000000000.0f;
        ull r0 = in0 ? (((ull)ordf(v0) << 32) | (unsigned)(2047 - e0))      : 0ull;
        ull r1 = in1 ? (((ull)ordf(v1) << 32) | (unsigned)(2047 - (e0+32))) : 0ull;
        sort2048(r0, r1, keys, tid, lane, e0);   // ends with __syncthreads()

        if (tid == 0) {
            int pc = min(s_totpos, PP);                 // pos_count
            int negtotal = NN - s_totpos;               // count of m < 0.5
            int nt = (int)(__fmul_rn((float)pc, R_POS)) - pc;  // XLA: mul by 1/0.33
            nt = max(0, min(nt, TPN));
            s_negn = min(nt, negtotal);
        }
        __syncthreads();

        if (tid < TPN) {
            int idx = 2047 - (int)(keys[tid] & 0xFFFFFFFFull);
            float valid = (tid < s_negn) ? 1.0f : 0.0f;
            const float* pb = props + (size_t)(b*NN+idx)*4;
            int row = b*TT + PP + tid;
            out[ROIS_OFF + row*4 + 0] = __fmul_rn(pb[0], valid);
            out[ROIS_OFF + row*4 + 1] = __fmul_rn(pb[1], valid);
            out[ROIS_OFF + row*4 + 2] = __fmul_rn(pb[2], valid);
            out[ROIS_OFF + row*4 + 3] = __fmul_rn(pb[3], valid);
            out[CLS_OFF + row] = 0.0f;
            out[DELTA_OFF + row*4 + 0] = 0.0f;
            out[DELTA_OFF + row*4 + 1] = 0.0f;
            out[DELTA_OFF + row*4 + 2] = 0.0f;
            out[DELTA_OFF + row*4 + 3] = 0.0f;
        }
    }
}

// ---------------------------------------------------------------------------
// K3: mask crops, sub-tiled. grid (PP*MSUB, BB), 256 threads.
// Streaming loads (__ldcs): zero reuse, don't pollute caches.
// ---------------------------------------------------------------------------
__global__ void __launch_bounds__(256) k_masks(const float* __restrict__ gmasks,
                                               float* __restrict__ out) {
    int t = blockIdx.x / MSUB, sub = blockIdx.x % MSUB;
    int b = blockIdx.y;
    float* om = out + MASK_OFF + (size_t)(b*TT + t) * (MHH*MWW) + sub*MPIX;
    int tid = threadIdx.x;

    if (d_posvalid[b*PP + t] == 0.0f) {
        if (tid < MPIX/4) ((float4*)om)[tid] = make_float4(0.f,0.f,0.f,0.f);
        return;
    }
    int g = d_posassign[b*PP + t];

    __shared__ float wy[MROWS], wx[MWW];
    __shared__ int y0i[MROWS], y1i[MROWS], x0i[MWW], x1i[MWW];

    float by1 = d_posbox[(b*PP+t)*4+0];
    float bx1 = d_posbox[(b*PP+t)*4+1];
    float by2 = d_posbox[(b*PP+t)*4+2];
    float bx2 = d_posbox[(b*PP+t)*4+3];

    if (tid < MROWS) {
        int i = sub*MROWS + tid;            // global row index
        float s  = __fmul_rn(__fmul_rn(__fsub_rn(by2,by1), (float)i), R_27);
        float yv = __fmul_rn(__fadd_rn(by1, s), 511.0f);
        float y0 = floorf(yv);
        wy[tid] = __fsub_rn(yv, y0);
        float c0 = fminf(fmaxf(y0, 0.0f), 511.0f);
        float c1 = fminf(fmaxf(__fadd_rn(y0, 1.0f), 0.0f), 511.0f);
        y0i[tid] = (int)c0; y1i[tid] = (int)c1;
    } else if (tid < MROWS + MWW) {
        int j = tid - MROWS;
        float s  = __fmul_rn(__fmul_rn(__fsub_rn(bx2,bx1), (float)j), R_27);
        float xv = __fmul_rn(__fadd_rn(bx1, s), 511.0f);
        float x0 = floorf(xv);
        wx[j] = __fsub_rn(xv, x0);
        float c0 = fminf(fmaxf(x0, 0.0f), 511.0f);
        float c1 = fminf(fmaxf(__fadd_rn(x0, 1.0f), 0.0f), 511.0f);
        x0i[j] = (int)c0; x1i[j] = (int)c1;
    }
    __syncthreads();

    if (tid < MPIX) {
        int ly = tid / MWW, xx = tid % MWW;   // local row, column
        const float* base = gmasks + (size_t)b*HH*WW*GG + g;
        int ya = y0i[ly], yb = y1i[ly], xa = x0i[xx], xb = x1i[xx];
        float v00 = __ldcs(&base[((size_t)ya*WW + xa)*GG]);
        float v01 = __ldcs(&base[((size_t)ya*WW + xb)*GG]);
        float v10 = __ldcs(&base[((size_t)yb*WW + xa)*GG]);
        float v11 = __ldcs(&base[((size_t)yb*WW + xb)*GG]);
        float fwx = wx[xx], fwy = wy[ly];
        float owx = __fsub_rn(1.0f, fwx);
        float owy = __fsub_rn(1.0f, fwy);
        float top = __fmaf_rn(v00, owx, __fmul_rn(v01, fwx));
        float bot = __fmaf_rn(v10, owx, __fmul_rn(v11, fwx));
        float r   = __fmaf_rn(top, owy, __fmul_rn(bot, fwy));
        om[tid] = rintf(r);
    }
}

// ---------------------------------------------------------------------------
extern "C" void kernel_launch(void* const* d_in, const int* in_sizes, int n_in,
                              void* d_out, int out_size) {
    const float* props  = (const float*)d_in[0];  // (B, N, 4)
    const int*   gids   = (const int*)  d_in[1];  // (B, G)
    const float* gboxes = (const float*)d_in[2];  // (B, G, 4)
    const float* gmasks = (const float*)d_in[3];  // (B, H, W, G)
    float* out = (float*)d_out;

    dim3 g1(IOU_BLKS + ZERO_BLKS, BB);
    k_iou<<<g1, 256>>>(props, gids, gboxes, out);
    dim3 g2(BB, 2);
    k_sortfin<<<g2, 1024>>>(props, gids, gboxes, out);
    dim3 g3(PP*MSUB, BB);
    k_masks<<<g3, 256>>>(gmasks, out);
}